// round 12
// baseline (speedup 1.0000x reference)
#include <cuda_runtime.h>
#include <cuda_fp16.h>
#include <cstdint>

// Correlation layer via band-restricted mma.sync (m16n8k16 fp16, fp32 accum).
// out[b, di*9+dj, h, w] = sum_c f1[b,c,h,w] * f2[b,c,h+di-4,w+dj-4]
// B=8, C=256, H=64, W=128, D=81.
//
// R12: one CTA per (h,b), 256 thr. 8 warps = 4 m32 w-blocks x 2 di-halves.
//      Per r: 6 MMAs from 3 LDSM ops (band tiles shared between the warp's
//      two m16 halves). f2: padded fp16 gmem pre-cast, 16B division-free
//      cp.async, 9 rows loaded once per CTA, NBUF=4. f1: fp32 LDG.128 x2 ->
//      pack -> STS.128 into a 4-slot fp16 ring inside the kernel (no f1 cast
//      pass). Coalesced epilogue.

#define NB 8
#define NC 256
#define NH 64
#define NW 128
#define ND 81
#define PW 136                       // padded f2 row (halves); data at cols [4,132)

#define RSTRIDE 272                  // smem c-row bytes (f2 and f1); %128==16 -> LDSM conflict-free
#define F2ROW (16 * RSTRIDE)         // 4352 B per r per 16-c chunk
#define F2CHUNK (9 * F2ROW)          // 39168 B: all 9 r rows
#define NBUF 4
#define OFF_F1 (NBUF * F2CHUNK)      // 156672
#define F1SLOT F2ROW                 // 4352 B per f1 chunk slot (16c x 136h)
#define SMEM_SZ (OFF_F1 + 4 * F1SLOT)   // 174080 B
#define STAGE_W 41                   // floats per staging row (40 band cols + pad)

__device__ __half g_f2h[(size_t)NB * NC * NH * PW];

// ---------------- fp32 -> padded fp16 cast for f2 ----------------
__global__ void cast_kernel(const float* __restrict__ f2) {
    int idx = blockIdx.x * 256 + threadIdx.x;   // one 16B output seg
    int row = idx / 17, sg = idx % 17;          // row = ((b*NC+c)*NH+h)
    const float* src = f2 + (size_t)row * NW;
    __half hv[8];
    #pragma unroll
    for (int k = 0; k < 8; k++) {
        int col = 8 * sg - 4 + k;
        float v = (col >= 0 && col < NW) ? src[col] : 0.0f;
        hv[k] = __float2half_rn(v);
    }
    *reinterpret_cast<uint4*>(g_f2h + (size_t)row * PW + 8 * sg) =
        *reinterpret_cast<const uint4*>(hv);
}

// ---------------- PTX helpers ----------------
__device__ __forceinline__ void cpa16(uint32_t dst, const void* src) {
    asm volatile("cp.async.ca.shared.global [%0], [%1], 16;" :: "r"(dst), "l"(src));
}
__device__ __forceinline__ void ldsm4t(uint32_t& r0, uint32_t& r1,
                                       uint32_t& r2, uint32_t& r3, uint32_t a) {
    asm volatile("ldmatrix.sync.aligned.m8n8.x4.trans.shared.b16 {%0,%1,%2,%3}, [%4];"
                 : "=r"(r0), "=r"(r1), "=r"(r2), "=r"(r3) : "r"(a));
}
__device__ __forceinline__ void ldsm2t(uint32_t& r0, uint32_t& r1, uint32_t a) {
    asm volatile("ldmatrix.sync.aligned.m8n8.x2.trans.shared.b16 {%0,%1}, [%2];"
                 : "=r"(r0), "=r"(r1) : "r"(a));
}
__device__ __forceinline__ void mma16816(float* d, const uint32_t* a,
                                         uint32_t b0, uint32_t b1) {
    asm volatile("mma.sync.aligned.m16n8k16.row.col.f32.f16.f16.f32 "
                 "{%0,%1,%2,%3}, {%4,%5,%6,%7}, {%8,%9}, {%0,%1,%2,%3};"
                 : "+f"(d[0]), "+f"(d[1]), "+f"(d[2]), "+f"(d[3])
                 : "r"(a[0]), "r"(a[1]), "r"(a[2]), "r"(a[3]), "r"(b0), "r"(b1));
}
__device__ __forceinline__ uint32_t pkh2(float lo, float hi) {
    __half2 h = __floats2half2_rn(lo, hi);
    return *reinterpret_cast<uint32_t*>(&h);
}

// ---------------- main kernel ----------------
__global__ void __launch_bounds__(256, 1)
corr_mma(const float* __restrict__ f1, float* __restrict__ out) {
    extern __shared__ char smem[];
    const uint32_t sb = (uint32_t)__cvta_generic_to_shared(smem);
    const int tid = threadIdx.x;
    const int lane = tid & 31, warp = tid >> 5;
    const int q = warp & 3, half = warp >> 2;   // m32 w-block 32q; di-half
    const int h = blockIdx.x, b = blockIdx.y;

    const int R0 = half ? 4 : 0;
    const int RN = half ? 5 : 4;

    float acc[5][6][4];
    #pragma unroll
    for (int ri = 0; ri < 5; ri++)
        #pragma unroll
        for (int t = 0; t < 6; t++)
            #pragma unroll
            for (int k = 0; k < 4; k++)
                acc[ri][t][k] = 0.0f;

    // ldmatrix lane addressing.
    // A (.trans on [c][w]): mat q2: rows c = (lane&7)+8*(lane>>4), col w +8*((lane>>3)&1)
    const uint32_t a_off = (uint32_t)((lane & 7) + ((lane >> 4) << 3)) * RSTRIDE
                         + ((32 * q + 8 * ((lane >> 3) & 1)) << 1);
    // B x4 pair (tiles at cols X, X+8): rows c = lane&15, col +8 for lanes>=16
    const uint32_t b4_off = (uint32_t)(lane & 15) * RSTRIDE + ((lane >> 4) << 4) + 64 * q;
    const uint32_t b2_off = (uint32_t)(lane & 15) * RSTRIDE + 64 * q + 64;  // tile at col 32q+32

    // f2 loader (division-free): thread (ci, sg) copies seg sg of all 9 rows;
    // sg==0 threads also copy seg 16.
    const int ci = tid >> 4, sg = tid & 15;
    auto issue = [&](int cc) {
        const int c0 = cc * 16;
        const uint32_t dbase = sb + (cc & (NBUF - 1)) * F2CHUNK;
        #pragma unroll
        for (int r = 0; r < 9; r++) {
            int gr = h + r - 4;
            gr = gr < 0 ? 0 : (gr > NH - 1 ? NH - 1 : gr);  // clamp; invalid di never stored
            const __half* rowp = g_f2h + ((size_t)(b * NC + c0 + ci) * NH + gr) * PW;
            const uint32_t d = dbase + r * F2ROW + ci * RSTRIDE;
            cpa16(d + 16 * sg, rowp + 8 * sg);
            if (sg == 0) cpa16(d + 256, rowp + 128);
        }
    };

    // f1: LDG fp32 (2x float4) for chunk cc into regs.
    const float* f1base = f1 + ((size_t)b * NC + ci) * (NH * NW) + h * NW + 8 * sg;
    float4 v0, v1;
    auto ldf1 = [&](int cc) {
        const float* p = f1base + (size_t)cc * 16 * (NH * NW);
        v0 = __ldg((const float4*)p);
        v1 = __ldg((const float4*)(p + 4));
    };
    // STS packed fp16 into f1 slot (published by the next __syncthreads).
    auto stf1 = [&](int cc) {
        uint4 pk;
        pk.x = pkh2(v0.x, v0.y); pk.y = pkh2(v0.z, v0.w);
        pk.z = pkh2(v1.x, v1.y); pk.w = pkh2(v1.z, v1.w);
        uint32_t d = sb + OFF_F1 + (cc & 3) * F1SLOT + ci * RSTRIDE + 16 * sg;
        asm volatile("st.shared.v4.b32 [%0], {%1,%2,%3,%4};"
                     :: "r"(d), "r"(pk.x), "r"(pk.y), "r"(pk.z), "r"(pk.w) : "memory");
    };

    // prologue
    ldf1(0);
    issue(0); asm volatile("cp.async.commit_group;");
    issue(1); asm volatile("cp.async.commit_group;");
    issue(2); asm volatile("cp.async.commit_group;");
    stf1(0);
    ldf1(1);

    for (int cc = 0; cc < 16; cc++) {
        asm volatile("cp.async.wait_group 2;");   // f2 chunk cc complete
        __syncthreads();                          // publishes f2 cc and f1 slot cc
        if (cc + 3 < 16) issue(cc + 3);           // buf (cc+3)&3 == (cc-1)&3: consumed pre-barrier
        asm volatile("cp.async.commit_group;");   // empty at tail keeps count uniform
        if (cc + 1 < 16) stf1(cc + 1);            // regs from ldf1(cc+1), one iter old
        if (cc + 2 < 16) ldf1(cc + 2);

        const uint32_t f1s = sb + OFF_F1 + (cc & 3) * F1SLOT;
        uint32_t a[8];
        ldsm4t(a[0], a[1], a[2], a[3], f1s + a_off);        // A0: w 32q..+16
        ldsm4t(a[4], a[5], a[6], a[7], f1s + a_off + 32);   // A1: w 32q+16..+32
        const uint32_t cbase = sb + (cc & (NBUF - 1)) * F2CHUNK;
        #pragma unroll
        for (int ri = 0; ri < 5; ri++) {
            if (ri < RN) {
                const uint32_t rb = cbase + (R0 + ri) * F2ROW;
                uint32_t bq[8], e0, e1;
                ldsm4t(bq[0], bq[1], bq[2], bq[3], rb + b4_off);        // tiles 0,1
                ldsm4t(bq[4], bq[5], bq[6], bq[7], rb + b4_off + 32);   // tiles 2,3
                ldsm2t(e0, e1, rb + b2_off);                            // tile 4
                mma16816(acc[ri][0], a,     bq[0], bq[1]);   // A0 x t0
                mma16816(acc[ri][1], a,     bq[2], bq[3]);   // A0 x t1
                mma16816(acc[ri][2], a,     bq[4], bq[5]);   // A0 x t2
                mma16816(acc[ri][3], a + 4, bq[4], bq[5]);   // A1 x t2
                mma16816(acc[ri][4], a + 4, bq[6], bq[7]);   // A1 x t3
                mma16816(acc[ri][5], a + 4, e0, e1);         // A1 x t4
            }
        }
    }

    // ---------------- epilogue: band extraction via per-warp staging ----------------
    __syncthreads();   // buffers dead; staging aliases them
    float* stage = reinterpret_cast<float*>(smem) + warp * 32 * STAGE_W;
    const int gid = lane >> 2, tig = lane & 3;
    #pragma unroll
    for (int ri = 0; ri < 5; ri++) {
        if (ri < RN) {
            const int r = R0 + ri;
            // A0 tiles t0-2 -> rows gid(+8),   band cols 8t + 2tig(+1)
            // A1 tiles t3-5 -> rows 16+gid(+8), band cols 8(t-2)+8... t3->16, t4->24, t5->32
            #pragma unroll
            for (int t = 0; t < 3; t++) {
                float* s0 = stage + gid * STAGE_W + 8 * t + 2 * tig;
                s0[0] = acc[ri][t][0];  s0[1] = acc[ri][t][1];
                s0[8 * STAGE_W] = acc[ri][t][2];  s0[8 * STAGE_W + 1] = acc[ri][t][3];
                float* s1 = stage + (16 + gid) * STAGE_W + 8 * (t + 2) + 2 * tig;
                s1[0] = acc[ri][t + 3][0];  s1[1] = acc[ri][t + 3][1];
                s1[8 * STAGE_W] = acc[ri][t + 3][2];  s1[8 * STAGE_W + 1] = acc[ri][t + 3][3];
            }
            __syncwarp();
            const int gr = h + r - 4;
            const bool valid = (gr >= 0 && gr < NH);
            // out[b, r*9+dj, h, 32q+lane] = stage[lane][lane+dj]
            const float* srow = stage + lane * STAGE_W + lane;
            float* obase = out + (((size_t)b * ND + r * 9) * NH + h) * NW + 32 * q + lane;
            #pragma unroll
            for (int dj = 0; dj < 9; dj++)
                obase[(size_t)dj * NH * NW] = valid ? srow[dj] : 0.0f;
            __syncwarp();
        }
    }
}

extern "C" void kernel_launch(void* const* d_in, const int* in_sizes, int n_in,
                              void* d_out, int out_size) {
    const float* f1 = (const float*)d_in[0];
    const float* f2 = (const float*)d_in[1];
    float* out = (float*)d_out;

    cudaFuncSetAttribute(corr_mma, cudaFuncAttributeMaxDynamicSharedMemorySize, SMEM_SZ);

    // (NB*NC*NH rows) * 17 segs / 256 threads = 8704 blocks exactly
    cast_kernel<<<8704, 256>>>(f2);
    corr_mma<<<dim3(NH, NB), 256, SMEM_SZ>>>(f1, out);
}